// round 17
// baseline (speedup 1.0000x reference)
#include <cuda_runtime.h>
#include <cuda_bf16.h>
#include <cstdint>

// CRF loss via tensor cores. B=2048, L=512, T=32.
// Block = 4 warps, 16 batches = rows of m16n8k16 mma (bf16 in, f32 accum).
//   fwd (bid<128):  x' = (x @ M) . w,   M[i][j]=exp(trans[i][j]), steps [0,m)
//   bwd (bid>=128): y' = (y . w) @ M^T, steps from row len-1 down to m
// D-fragment == next A-fragment (no cross-thread movement per step).
// Warp 0 = consumer (mma chain); warps 1-3 = producers (exp(emit) -> smem in
// fragment layout; 24-step phases, double buffered, 1 barrier per phase).
// Per-row renorm every 2 steps (scale in log2); per-row freeze via select.
// Kernel 2: gold score + combine.

#define CRF_B 2048
#define CRF_L 512
#define CRF_T 32
#define GRP   16
#define NGRP  (CRF_B / GRP)   // 128
#define PH    24              // steps per phase
#define WBUF_U32 (2 * PH * 32 * 8)   // 12288 u32 = 48KB

__device__ float g_aF[CRF_B * CRF_T];
__device__ float g_bB[CRF_B * CRF_T];
__device__ float g_MlF[CRF_B];
__device__ float g_MlB[CRF_B];

#define FULLM 0xffffffffu

__device__ __forceinline__ unsigned pkbf(float lo, float hi) {
    unsigned r; asm("cvt.rn.bf16x2.f32 %0, %1, %2;" : "=r"(r) : "f"(hi), "f"(lo));
    return r;  // .lo=lo, .hi=hi
}
__device__ __forceinline__ float bflo(unsigned u) { return __uint_as_float(u << 16); }
__device__ __forceinline__ float bfhi(unsigned u) { return __uint_as_float(u & 0xffff0000u); }

__device__ __forceinline__ void mma16816(float d[4], const unsigned a[4],
                                         const unsigned b[2], const float c[4]) {
    asm volatile("mma.sync.aligned.m16n8k16.row.col.f32.bf16.bf16.f32 "
                 "{%0,%1,%2,%3}, {%4,%5,%6,%7}, {%8,%9}, {%10,%11,%12,%13};"
                 : "=f"(d[0]), "=f"(d[1]), "=f"(d[2]), "=f"(d[3])
                 : "r"(a[0]), "r"(a[1]), "r"(a[2]), "r"(a[3]),
                   "r"(b[0]), "r"(b[1]),
                   "f"(c[0]), "f"(c[1]), "f"(c[2]), "f"(c[3]));
}

__global__ __launch_bounds__(128)
void crf_mma_kernel(const float* __restrict__ emit,
                    const float* __restrict__ trans,
                    const int*   __restrict__ lengths)
{
    extern __shared__ unsigned wbuf[];   // [2][PH][32][8]
    const int  tid  = threadIdx.x;
    const int  wid  = tid >> 5;
    const int  lane = tid & 31;
    const int  gr   = lane >> 2;   // fragment row group (0..7)
    const int  cq   = lane & 3;    // fragment quad col (0..3)
    const bool bwd  = blockIdx.x >= NGRP;
    const int  base = (bwd ? blockIdx.x - NGRP : blockIdx.x) * GRP;

    int lnl = 0;
    if (lane < GRP) lnl = __ldg(&lengths[base + lane]);
    int stepl = bwd ? (lnl >> 1) : ((lnl + 1) >> 1);   // steps this batch needs
    int Smax = stepl;
#pragma unroll
    for (int off = 16; off; off >>= 1)
        Smax = max(Smax, __shfl_xor_sync(FULLM, Smax, off));
    const int P = (Smax + PH - 1) / PH;

    const int len_lo = __shfl_sync(FULLM, lnl, gr);
    const int len_hi = __shfl_sync(FULLM, lnl, gr + 8);
    const int lim_lo = bwd ? (len_lo >> 1) : ((len_lo + 1) >> 1);
    const int lim_hi = bwd ? (len_hi >> 1) : ((len_hi + 1) >> 1);

    if (wid != 0) {
        // ---------------- PRODUCER (warps 1..3) ----------------
        // phase p, this warp fills steps 24p + 8*(wid-1) + 0..7
        auto fill = [&](int p) {
#pragma unroll 1
            for (int k8 = 0; k8 < 8; k8++) {
                const int kph = (wid - 1) * 8 + k8;
                const int s = p * PH + kph;
                if (s >= Smax) break;
                unsigned o[8];
#pragma unroll
                for (int h = 0; h < 2; h++) {
                    const int lenh = h ? len_hi : len_lo;
                    const int t = bwd ? max(lenh - 1 - s, 0) : s;
                    const float* src = emit +
                        ((size_t)(base + gr + 8 * h) * CRF_L + t) * CRF_T + 2 * cq;
#pragma unroll
                    for (int j = 0; j < 4; j++) {
                        float2 v = *(const float2*)(src + 8 * j);
                        o[h * 4 + j] = pkbf(__expf(v.x), __expf(v.y));
                    }
                }
                unsigned idx = (((unsigned)(p & 1) * PH + kph) * 32 + lane) * 8;
                *(uint4*)&wbuf[idx]     = make_uint4(o[0], o[1], o[2], o[3]);
                *(uint4*)&wbuf[idx + 4] = make_uint4(o[4], o[5], o[6], o[7]);
            }
        };
        fill(0);
        __syncthreads();
        for (int p = 0; p < P; p++) {
            if (p + 1 < P) fill(p + 1);
            __syncthreads();
        }
    } else {
        // ---------------- CONSUMER (warp 0) ----------------
        // B fragments: 2 k-tiles x 4 n-tiles x 2 regs.
        unsigned Bf[16];
#pragma unroll
        for (int kt = 0; kt < 2; kt++)
#pragma unroll
            for (int j = 0; j < 4; j++) {
                const int n = 8 * j + gr;
                const int k = 16 * kt + 2 * cq;
                float b00, b01, b10, b11;
                if (!bwd) {
                    b00 = __expf(__ldg(&trans[(k + 0) * CRF_T + n]));
                    b01 = __expf(__ldg(&trans[(k + 1) * CRF_T + n]));
                    b10 = __expf(__ldg(&trans[(k + 8) * CRF_T + n]));
                    b11 = __expf(__ldg(&trans[(k + 9) * CRF_T + n]));
                } else {
                    b00 = __expf(__ldg(&trans[n * CRF_T + k + 0]));
                    b01 = __expf(__ldg(&trans[n * CRF_T + k + 1]));
                    b10 = __expf(__ldg(&trans[n * CRF_T + k + 8]));
                    b11 = __expf(__ldg(&trans[n * CRF_T + k + 9]));
                }
                Bf[(kt * 4 + j) * 2 + 0] = pkbf(b00, b01);
                Bf[(kt * 4 + j) * 2 + 1] = pkbf(b10, b11);
            }

        // x[(h*4+j)*2+e] = value at row gr+8h, col 8j+2cq+e
        float x[16];
#pragma unroll
        for (int i = 0; i < 16; i++) x[i] = 1.0f;   // bwd init: beta = 1
        float Ml_lo = 0.f, Ml_hi = 0.f;

        __syncthreads();   // phase 0 ready
        for (int p = 0; p < P; p++) {
#pragma unroll 1
            for (int k = 0; k < PH; k++) {
                const int s = p * PH + k;
                if (s >= Smax) break;
                unsigned idx = (((unsigned)(p & 1) * PH + k) * 32 + lane) * 8;
                uint4 wa = *(uint4*)&wbuf[idx];
                uint4 wb = *(uint4*)&wbuf[idx + 4];
                unsigned w8[8] = {wa.x, wa.y, wa.z, wa.w, wb.x, wb.y, wb.z, wb.w};
                float wf[16];
#pragma unroll
                for (int i = 0; i < 8; i++) {
                    wf[2 * i]     = bflo(w8[i]);
                    wf[2 * i + 1] = bfhi(w8[i]);
                }

                if (!bwd && s == 0) {
#pragma unroll
                    for (int i = 0; i < 16; i++) x[i] = wf[i];  // alpha_0 = w_0
                } else {
                    float sv[16];
#pragma unroll
                    for (int i = 0; i < 16; i++)
                        sv[i] = bwd ? x[i] * wf[i] : x[i];
                    unsigned a0[4] = { pkbf(sv[0], sv[1]),  pkbf(sv[8],  sv[9]),
                                       pkbf(sv[2], sv[3]),  pkbf(sv[10], sv[11]) };
                    unsigned a1[4] = { pkbf(sv[4], sv[5]),  pkbf(sv[12], sv[13]),
                                       pkbf(sv[6], sv[7]),  pkbf(sv[14], sv[15]) };
                    const float zc[4] = {0.f, 0.f, 0.f, 0.f};
                    float d[4][4];
#pragma unroll
                    for (int j = 0; j < 4; j++) {
                        mma16816(d[j], a0, &Bf[j * 2], zc);
                        mma16816(d[j], a1, &Bf[(4 + j) * 2], d[j]);
                    }
                    const bool alo = s < lim_lo;
                    const bool ahi = s < lim_hi;
#pragma unroll
                    for (int j = 0; j < 4; j++) {
                        float n0 = bwd ? d[j][0] : d[j][0] * wf[2 * j];
                        float n1 = bwd ? d[j][1] : d[j][1] * wf[2 * j + 1];
                        float n2 = bwd ? d[j][2] : d[j][2] * wf[8 + 2 * j];
                        float n3 = bwd ? d[j][3] : d[j][3] * wf[8 + 2 * j + 1];
                        if (alo) { x[2 * j] = n0;     x[2 * j + 1] = n1; }
                        if (ahi) { x[8 + 2 * j] = n2; x[8 + 2 * j + 1] = n3; }
                    }
                }
                if (s & 1) {   // per-row renorm (invariant-preserving)
                    const float g0 = __shfl_sync(FULLM, x[0], lane & ~3);
                    const float g1 = __shfl_sync(FULLM, x[8], lane & ~3);
                    float r0, r1;
                    asm("rcp.approx.f32 %0, %1;" : "=f"(r0) : "f"(g0));
                    asm("rcp.approx.f32 %0, %1;" : "=f"(r1) : "f"(g1));
                    Ml_lo += __log2f(g0);
                    Ml_hi += __log2f(g1);
#pragma unroll
                    for (int i = 0; i < 8; i++) { x[i] *= r0; x[8 + i] *= r1; }
                }
            }
            __syncthreads();
        }

        float* dst = bwd ? g_bB : g_aF;
#pragma unroll
        for (int h = 0; h < 2; h++)
#pragma unroll
            for (int j = 0; j < 4; j++)
#pragma unroll
                for (int e = 0; e < 2; e++)
                    dst[(base + gr + 8 * h) * CRF_T + 8 * j + 2 * cq + e]
                        = x[(h * 4 + j) * 2 + e];
        if (cq == 0) {
            float* Mdst = bwd ? g_MlB : g_MlF;
            Mdst[base + gr]     = Ml_lo;
            Mdst[base + gr + 8] = Ml_hi;
        }
    }
}

__global__ __launch_bounds__(256)
void crf_gold_kernel(const float* __restrict__ emit,
                     const float* __restrict__ trans,
                     const int*   __restrict__ tags,
                     const int*   __restrict__ lengths,
                     float*       __restrict__ out)
{
    const int lane = threadIdx.x & 31;
    const int b = (blockIdx.x * blockDim.x + threadIdx.x) >> 5;
    if (b >= CRF_B) return;
    const int len = __ldg(&lengths[b]);

    float gs = 0.f;
    for (int l = lane; l < len; l += 32) {
        const int tg = __ldg(&tags[b * CRF_L + l]);
        gs += __ldg(&emit[((size_t)b * CRF_L + l) * CRF_T + tg]);
        if (l >= 1) {
            const int tp = __ldg(&tags[b * CRF_L + l - 1]);
            gs += __ldg(&trans[tp * CRF_T + tg]);
        }
    }
    float prod = g_aF[b * CRF_T + lane] * g_bB[b * CRF_T + lane];
#pragma unroll
    for (int off = 16; off; off >>= 1) {
        gs   += __shfl_xor_sync(FULLM, gs, off);
        prod += __shfl_xor_sync(FULLM, prod, off);
    }
    if (lane == 0)
        out[b] = (g_MlF[b] + g_MlB[b]) * 0.6931471805599453f + __logf(prod) - gs;
}

extern "C" void kernel_launch(void* const* d_in, const int* in_sizes, int n_in,
                              void* d_out, int out_size)
{
    const float* emit    = (const float*)d_in[0];
    const float* trans   = (const float*)d_in[1];
    const int*   tags    = (const int*)d_in[2];
    const int*   lengths = (const int*)d_in[3];
    float*       out     = (float*)d_out;

    (void)in_sizes; (void)n_in; (void)out_size;

    crf_mma_kernel<<<2 * NGRP, 128, WBUF_U32 * sizeof(unsigned)>>>(emit, trans, lengths);
    crf_gold_kernel<<<CRF_B / 8, 256>>>(emit, trans, tags, lengths, out);
}